// round 14
// baseline (speedup 1.0000x reference)
#include <cuda_runtime.h>
#include <cuda_fp16.h>
#include <math.h>
#include <stdint.h>

// ---------------- problem constants ----------------
#define NBATCH   2
#define LSEQ     2048
#define TT       4096            // NBATCH*LSEQ tokens
#define DMODEL   1024
#define DINNER   2048
#define DSTATE   16
#define DTRANK   64
#define NEXPERT  8
#define FFND     4096
#define LDDBC    128             // padded DT_RANK + 2*D_STATE (96 -> 128)
#define MAXR     9216            // 2*TT + 8*128 padding headroom (multiple of 128)
#define KSPL     8               // split-K factor for x_proj

// ---------------- scratch (device globals; no allocation allowed) ----------
// fp32 buffers (scan recurrence / residual path)
__device__ float g_dbc[(size_t)TT * LDDBC];
__device__ float g_part[(size_t)KSPL * TT * LDDBC];   // x_proj split-K partials
__device__ float g_delta[(size_t)TT * DINNER];
__device__ float g_h2 [(size_t)TT * DMODEL];
__device__ float g_hn [(size_t)TT * DMODEL];
__device__ float g_Y  [(size_t)MAXR * DMODEL];
// fp16 activation buffers
__device__ __half g_h1h [(size_t)TT * DMODEL];
__device__ __half g_xzh [(size_t)TT * 2 * DINNER];
__device__ __half g_xich[(size_t)TT * DINNER];
__device__ __half g_dbch[(size_t)TT * LDDBC];
__device__ __half g_y2h [(size_t)TT * DINNER];
__device__ __half g_Xgh [(size_t)MAXR * DMODEL];
__device__ __half g_Gh0 [(size_t)MAXR * FFND];   // gate (pre-silu)
__device__ __half g_Gh  [(size_t)MAXR * FFND];   // silu(gate)*up
// fp16 weights, ORIGINAL [K][N] layout (B operands via ldmatrix.trans)
__device__ __half g_ipwh[(size_t)DMODEL * (2 * DINNER)];
__device__ __half g_xpwh[(size_t)DINNER * LDDBC];        // padded cols 96->128
__device__ __half g_dtwh[(size_t)DTRANK * DINNER];
__device__ __half g_opwh[(size_t)DINNER * DMODEL];
__device__ __half g_Wgh [(size_t)NEXPERT * DMODEL * FFND];
__device__ __half g_Wuh [(size_t)NEXPERT * DMODEL * FFND];
__device__ __half g_Wdh [(size_t)NEXPERT * FFND * DMODEL];
// MoE routing
__device__ int   g_sel[TT * 2];
__device__ float g_wts[TT * 2];
__device__ int   g_cnt[NEXPERT];
__device__ int   g_cur[NEXPERT];
__device__ int   g_seg[NEXPERT + 1];
__device__ int   g_tok[MAXR];
__device__ int   g_rowmap[TT * 2];

// ---------------- helpers ----------------
__device__ __forceinline__ float siluf(float x) { return x / (1.0f + __expf(-x)); }
__device__ __forceinline__ float softplusf(float x) {
    return (x > 20.0f) ? x : log1pf(__expf(x));
}
__device__ __forceinline__ void cp16(uint32_t sdst, const void* g) {
    asm volatile("cp.async.cg.shared.global [%0], [%1], 16;" :: "r"(sdst), "l"(g));
}
__device__ __forceinline__ void ldsm_x4(unsigned* r, uint32_t saddr) {
    asm volatile(
        "ldmatrix.sync.aligned.m8n8.x4.shared.b16 {%0,%1,%2,%3}, [%4];\n"
        : "=r"(r[0]), "=r"(r[1]), "=r"(r[2]), "=r"(r[3]) : "r"(saddr));
}
__device__ __forceinline__ void ldsm_x4t(unsigned* r, uint32_t saddr) {
    asm volatile(
        "ldmatrix.sync.aligned.m8n8.x4.trans.shared.b16 {%0,%1,%2,%3}, [%4];\n"
        : "=r"(r[0]), "=r"(r[1]), "=r"(r[2]), "=r"(r[3]) : "r"(saddr));
}
__device__ __forceinline__ void mma_f16(float* c, const unsigned* a, const unsigned* b) {
    asm volatile(
        "mma.sync.aligned.m16n8k16.row.col.f32.f16.f16.f32 "
        "{%0,%1,%2,%3},{%4,%5,%6,%7},{%8,%9},{%0,%1,%2,%3};\n"
        : "+f"(c[0]), "+f"(c[1]), "+f"(c[2]), "+f"(c[3])
        : "r"(a[0]), "r"(a[1]), "r"(a[2]), "r"(a[3]), "r"(b[0]), "r"(b[1]));
}

// ---------------- rmsnorm: one block per row; fp32 or fp16 out ----------------
__global__ void __launch_bounds__(256) k_rmsnorm(const float* __restrict__ x,
                                                 const float* __restrict__ w,
                                                 float* __restrict__ o,
                                                 __half* __restrict__ oh)
{
    __shared__ float red[8];
    const int r = blockIdx.x, tid = threadIdx.x;
    const float* xr = x + (size_t)r * DMODEL;
    float s = 0.f;
    #pragma unroll
    for (int i = 0; i < DMODEL / 256; i++) {
        float v = xr[tid + i * 256];
        s += v * v;
    }
    #pragma unroll
    for (int off = 16; off; off >>= 1) s += __shfl_xor_sync(0xffffffff, s, off);
    if ((tid & 31) == 0) red[tid >> 5] = s;
    __syncthreads();
    if (tid < 8) {
        float v = red[tid];
        #pragma unroll
        for (int off = 4; off; off >>= 1) v += __shfl_xor_sync(0xff, v, off);
        if (tid == 0) red[0] = v;
    }
    __syncthreads();
    const float rms = rsqrtf(red[0] * (1.0f / DMODEL) + 1e-5f);
    #pragma unroll
    for (int i = 0; i < DMODEL / 256; i++) {
        const int c = tid + i * 256;
        const float v = xr[c] * rms * w[c];
        if (oh) oh[(size_t)r * DMODEL + c] = __float2half(v);
        else    o [(size_t)r * DMODEL + c] = v;
    }
}

// ---------------- fused rmsnorm2 + router (one block per token) --------------
__global__ void __launch_bounds__(256) k_rms_router(const float* __restrict__ x,
                                                    const float* __restrict__ w,
                                                    float* __restrict__ o,
                                                    const float* __restrict__ rw)
{
    __shared__ float red[8];
    __shared__ float sred[8][NEXPERT];
    const int r = blockIdx.x, tid = threadIdx.x;
    const int warp = tid >> 5, lane = tid & 31;
    const float* xr = x + (size_t)r * DMODEL;
    float s = 0.f;
    #pragma unroll
    for (int i = 0; i < DMODEL / 256; i++) {
        float v = xr[tid + i * 256];
        s += v * v;
    }
    #pragma unroll
    for (int off = 16; off; off >>= 1) s += __shfl_xor_sync(0xffffffff, s, off);
    if (lane == 0) red[warp] = s;
    __syncthreads();
    if (tid < 8) {
        float v = red[tid];
        #pragma unroll
        for (int off = 4; off; off >>= 1) v += __shfl_xor_sync(0xff, v, off);
        if (tid == 0) red[0] = v;
    }
    __syncthreads();
    const float rms = rsqrtf(red[0] * (1.0f / DMODEL) + 1e-5f);

    float lg[NEXPERT];
    #pragma unroll
    for (int e = 0; e < NEXPERT; e++) lg[e] = 0.f;
    #pragma unroll
    for (int i = 0; i < DMODEL / 256; i++) {
        const int c = tid + i * 256;
        const float v = xr[c] * rms * w[c];
        o[(size_t)r * DMODEL + c] = v;
        #pragma unroll
        for (int e = 0; e < NEXPERT; e++) lg[e] += v * rw[c * NEXPERT + e];
    }
    #pragma unroll
    for (int off = 16; off; off >>= 1)
        #pragma unroll
        for (int e = 0; e < NEXPERT; e++)
            lg[e] += __shfl_xor_sync(0xffffffff, lg[e], off);
    if (lane == 0)
        #pragma unroll
        for (int e = 0; e < NEXPERT; e++) sred[warp][e] = lg[e];
    __syncthreads();
    if (tid == 0) {
        float p[NEXPERT];
        #pragma unroll
        for (int e = 0; e < NEXPERT; e++) {
            float a = 0.f;
            #pragma unroll
            for (int wgi = 0; wgi < 8; wgi++) a += sred[wgi][e];
            p[e] = a;
        }
        float m = p[0];
        #pragma unroll
        for (int e = 1; e < NEXPERT; e++) m = fmaxf(m, p[e]);
        float sum = 0.f;
        #pragma unroll
        for (int e = 0; e < NEXPERT; e++) { p[e] = __expf(p[e] - m); sum += p[e]; }
        const float inv = 1.0f / sum;
        #pragma unroll
        for (int e = 0; e < NEXPERT; e++) p[e] *= inv;
        int i1 = 0;
        #pragma unroll
        for (int e = 1; e < NEXPERT; e++) if (p[e] > p[i1]) i1 = e;
        int i2 = (i1 == 0) ? 1 : 0;
        #pragma unroll
        for (int e = 0; e < NEXPERT; e++) if (e != i1 && p[e] > p[i2]) i2 = e;
        g_sel[r * 2] = i1; g_sel[r * 2 + 1] = i2;
        g_wts[r * 2] = p[i1]; g_wts[r * 2 + 1] = p[i2];
        atomicAdd(&g_cnt[i1], 1);
        atomicAdd(&g_cnt[i2], 1);
    }
}

// ---------------- coalesced fp32 -> fp16 convert, MLP=4 per thread ------------
__global__ void __launch_bounds__(256) k_cvt(const float* __restrict__ in,
                                             __half* __restrict__ out, int n4)
{
    const int base = blockIdx.x * 1024 + threadIdx.x;
    float4 v[4];
    #pragma unroll
    for (int j = 0; j < 4; j++)
        v[j] = reinterpret_cast<const float4*>(in)[base + j * 256];
    #pragma unroll
    for (int j = 0; j < 4; j++) {
        __half2* o = reinterpret_cast<__half2*>(out) + (size_t)(base + j * 256) * 2;
        o[0] = __floats2half2_rn(v[j].x, v[j].y);
        o[1] = __floats2half2_rn(v[j].z, v[j].w);
    }
}

// x_proj weight: [2048][96] fp32 -> [2048][128] fp16 (pad cols with 0)
__global__ void __launch_bounds__(256) k_cvtpad(const float* __restrict__ in,
                                                __half* __restrict__ out)
{
    const int i = blockIdx.x * 256 + threadIdx.x;   // over DINNER*128
    const int k = i >> 7, n = i & 127;
    out[i] = __float2half((n < 96) ? in[k * 96 + n] : 0.f);
}

// reduce KSPL split-K partials -> fp32 dbc + fp16 dbch
__global__ void __launch_bounds__(256) k_red8()
{
    const int i = blockIdx.x * 256 + threadIdx.x;   // over TT*LDDBC
    float s = 0.f;
    #pragma unroll
    for (int z = 0; z < KSPL; z++)
        s += g_part[(size_t)z * TT * LDDBC + i];
    g_dbc[i] = s;
    g_dbch[i] = __float2half(s);
}

// ---------------- fp16 tensor-core GEMM: C[M,N] = A[M,K] @ B[K,N] --------------
// A fp16 [M][K] row-major; B fp16 [K][N] row-major (fragments via ldmatrix.trans).
// 128x128x64 tiles, 8 warps (64x32 warp tiles), cp.async 3-stage pipeline.
// Split-K: when gridDim.z > 1 (and not grouped), blockIdx.z selects a K-slice
// of length K and writes to C + z*expStride (expStride reused as z-stride).
// mode 0: plain; 1: +aux32[row*ldc+col]; 2: softplus(acc+aux32[col]);
// mode 4: silu(aux16[row*ldc+col]) * acc.
// outKind 0: fp32 C; 1: fp16 Ch; 2: both.
#define TK     64
#define NSTG   3
#define ASTR   144                 // bytes per A smem row (64 halves + 8 pad)
#define BSTR   272                 // bytes per B smem row (128 halves + 8 pad)
#define ASTG   (128 * ASTR)        // 18432
#define BSTG   (TK * BSTR)         // 17408
#define H_SMEM (NSTG * (ASTG + BSTG)) // 107520

__global__ void __launch_bounds__(256, 2)
k_hgemm(const __half* __restrict__ A, const __half* __restrict__ Bbase,
        float* __restrict__ C, __half* __restrict__ Ch,
        int K, int lda, int ldb, int ldc,
        int mode, const void* __restrict__ aux, int outKind,
        int grouped, size_t expStride)
{
    const int m0 = blockIdx.y * 128;
    const int n0 = blockIdx.x * 128;
    const __half* B = Bbase;
    if (grouped) {
        if (m0 >= g_seg[NEXPERT]) return;
        int e = 0;
        while (g_seg[e + 1] <= m0) e++;
        B += (size_t)e * expStride;
    } else if (gridDim.z > 1) {
        const int kz = blockIdx.z;
        A += (size_t)kz * K;            // within-row K offset
        B += (size_t)kz * K * ldb;      // K-rows offset
        C += (size_t)kz * expStride;    // partials slab
    }

    extern __shared__ __align__(16) char hsm[];
    const uint32_t sb = (uint32_t)__cvta_generic_to_shared(hsm);
    const uint32_t sbB = sb + NSTG * ASTG;

    const int tid = threadIdx.x;
    const int wid = tid >> 5, lane = tid & 31;
    const int wm = (wid >> 2) * 64;
    const int wn = (wid & 3) * 32;
    const int lr = lane >> 2, lc = lane & 3;      // epilogue coords
    const int q = lane >> 3, r8 = lane & 7;       // ldmatrix quadrant coords

    const uint32_t aoff = (uint32_t)((wm + ((q & 1) << 3) + r8) * ASTR + ((q >> 1) << 4));
    const uint32_t boff = (uint32_t)((((q & 1) << 3) + r8) * BSTR + ((wn + ((q >> 1) << 3)) << 1));

    float acc[4][4][4];
    #pragma unroll
    for (int i = 0; i < 4; i++)
        #pragma unroll
        for (int j = 0; j < 4; j++)
            #pragma unroll
            for (int v = 0; v < 4; v++) acc[i][j][v] = 0.f;

    const int nIter = K / TK;

    auto issue = [&](int st, int k0) {
        #pragma unroll
        for (int w = 0; w < 4; w++) {       // A: 128 rows x 8 chunks
            const int id = tid + w * 256;
            const int row = id >> 3, ch = id & 7;
            cp16(sb + st * ASTG + row * ASTR + ch * 16,
                 A + (size_t)(m0 + row) * lda + k0 + ch * 8);
        }
        #pragma unroll
        for (int w = 0; w < 4; w++) {       // B: 64 k-rows x 16 chunks
            const int id = tid + w * 256;
            const int kr = id >> 4, ch = id & 15;
            cp16(sbB + st * BSTG + kr * BSTR + ch * 16,
                 B + (size_t)(k0 + kr) * ldb + n0 + ch * 8);
        }
        asm volatile("cp.async.commit_group;" ::: "memory");
    };

    issue(0, 0);
    if (nIter > 1) issue(1, TK);

    for (int it = 0; it < nIter; it++) {
        if (it + 2 < nIter) issue((it + 2) % NSTG, (it + 2) * TK);
        if (it + 3 <= nIter) {
            asm volatile("cp.async.wait_group 2;" ::: "memory");
        } else if (it + 2 <= nIter) {
            asm volatile("cp.async.wait_group 1;" ::: "memory");
        } else {
            asm volatile("cp.async.wait_group 0;" ::: "memory");
        }
        __syncthreads();

        const int st = it % NSTG;
        const uint32_t aBase = sb + st * ASTG + aoff;
        const uint32_t bBase = sbB + st * BSTG + boff;
        #pragma unroll
        for (int ks = 0; ks < 4; ks++) {
            unsigned a[4][4], bt[2][4];
            #pragma unroll
            for (int mt = 0; mt < 4; mt++)
                ldsm_x4(a[mt], aBase + mt * (16 * ASTR) + ks * 32);
            #pragma unroll
            for (int g = 0; g < 2; g++)
                ldsm_x4t(bt[g], bBase + ks * (16 * BSTR) + g * 32);
            #pragma unroll
            for (int mt = 0; mt < 4; mt++)
                #pragma unroll
                for (int nt = 0; nt < 4; nt++)
                    mma_f16(acc[mt][nt], a[mt], &bt[nt >> 1][(nt & 1) * 2]);
        }
        __syncthreads();
    }

    // epilogue
    const float* aux32 = (const float*)aux;
    const __half* aux16 = (const __half*)aux;
    #pragma unroll
    for (int mt = 0; mt < 4; mt++) {
        #pragma unroll
        for (int nt = 0; nt < 4; nt++) {
            const int row = m0 + wm + mt * 16 + lr;
            const int col = n0 + wn + nt * 8 + lc * 2;
            float2 v0 = make_float2(acc[mt][nt][0], acc[mt][nt][1]);   // row
            float2 v1 = make_float2(acc[mt][nt][2], acc[mt][nt][3]);   // row+8
            if (mode == 1) {
                const float2 r0 = *reinterpret_cast<const float2*>(aux32 + (size_t)row * ldc + col);
                const float2 r1 = *reinterpret_cast<const float2*>(aux32 + (size_t)(row + 8) * ldc + col);
                v0.x += r0.x; v0.y += r0.y;
                v1.x += r1.x; v1.y += r1.y;
            } else if (mode == 2) {
                const float b0 = aux32[col], b1 = aux32[col + 1];
                v0.x = softplusf(v0.x + b0); v0.y = softplusf(v0.y + b1);
                v1.x = softplusf(v1.x + b0); v1.y = softplusf(v1.y + b1);
            } else if (mode == 4) {
                const float2 g0 = __half22float2(
                    *reinterpret_cast<const __half2*>(aux16 + (size_t)row * ldc + col));
                const float2 g1 = __half22float2(
                    *reinterpret_cast<const __half2*>(aux16 + (size_t)(row + 8) * ldc + col));
                v0.x *= siluf(g0.x); v0.y *= siluf(g0.y);
                v1.x *= siluf(g1.x); v1.y *= siluf(g1.y);
            }
            if (outKind != 1) {
                *reinterpret_cast<float2*>(C + (size_t)row * ldc + col) = v0;
                *reinterpret_cast<float2*>(C + (size_t)(row + 8) * ldc + col) = v1;
            }
            if (outKind >= 1) {
                *reinterpret_cast<__half2*>(Ch + (size_t)row * ldc + col) =
                    __floats2half2_rn(v0.x, v0.y);
                *reinterpret_cast<__half2*>(Ch + (size_t)(row + 8) * ldc + col) =
                    __floats2half2_rn(v1.x, v1.y);
            }
        }
    }
}

// ---------------- causal depthwise conv + silu (fp16 in/out) ----------------
__global__ void __launch_bounds__(256) k_conv(const float* __restrict__ cw,
                                              const float* __restrict__ cb)
{
    const int idx = blockIdx.x * 256 + threadIdx.x;   // over TT*DINNER
    const int c = idx & (DINNER - 1);
    const int tg = idx >> 11;                          // token index
    const int l = tg & (LSEQ - 1);
    float acc = cb[c];
    #pragma unroll
    for (int k = 0; k < 4; k++) {
        const int dl = l - 3 + k;
        if (dl >= 0)
            acc += cw[c * 4 + k] *
                   __half2float(g_xzh[(size_t)(tg - 3 + k) * (2 * DINNER) + c]);
    }
    g_xich[(size_t)tg * DINNER + c] = __float2half(siluf(acc));
}

// ---------------- selective scan: 16 channels/block, 16 lanes/channel --------
__global__ void __launch_bounds__(256) k_scan(const float* __restrict__ A_log,
                                              const float* __restrict__ D_skip)
{
    const int b = blockIdx.x >> 7;               // batch
    const int cg = blockIdx.x & 127;             // channel group
    const int tid = threadIdx.x;
    const int c = cg * 16 + (tid >> 4);
    const int n = tid & 15;

    const float A = -__expf(A_log[c * DSTATE + n]);
    const float D = D_skip[c];
    float h = 0.f;

    const float*  dlt = g_delta + (size_t)b * LSEQ * DINNER + c;
    const __half* xin = g_xich  + (size_t)b * LSEQ * DINNER + c;
    const float*  dbc = g_dbc   + (size_t)b * LSEQ * LDDBC;
    const __half* zin = g_xzh   + (size_t)b * LSEQ * (2 * DINNER) + DINNER + c;
    __half* yout = g_y2h + (size_t)b * LSEQ * DINNER + c;

    for (int l = 0; l < LSEQ; l++) {
        const float d  = dlt[(size_t)l * DINNER];
        const float x  = __half2float(xin[(size_t)l * DINNER]);
        const float Bn = dbc[(size_t)l * LDDBC + DTRANK + n];
        const float Cn = dbc[(size_t)l * LDDBC + DTRANK + DSTATE + n];
        const float dA = __expf(d * A);
        h = dA * h + (d * x) * Bn;
        float v = h * Cn;
        v += __shfl_xor_sync(0xffffffff, v, 1);
        v += __shfl_xor_sync(0xffffffff, v, 2);
        v += __shfl_xor_sync(0xffffffff, v, 4);
        v += __shfl_xor_sync(0xffffffff, v, 8);
        if (n == 0) {
            const float z = __half2float(zin[(size_t)l * (2 * DINNER)]);
            yout[(size_t)l * DINNER] = __float2half((v + D * x) * siluf(z));
        }
    }
}

// ---------------- MoE bookkeeping ----------------
__global__ void k_zero8() { if (threadIdx.x < NEXPERT) g_cnt[threadIdx.x] = 0; }

__global__ void k_seg()
{
    int s = 0;
    g_seg[0] = 0;
    for (int e = 0; e < NEXPERT; e++) {
        g_cur[e] = s;
        s += ((g_cnt[e] + 127) / 128) * 128;
        g_seg[e + 1] = s;
    }
}

__global__ void __launch_bounds__(256) k_assign()
{
    const int idx = blockIdx.x * 256 + threadIdx.x;   // over TT*2
    const int e = g_sel[idx];
    const int r = atomicAdd(&g_cur[e], 1);
    g_tok[r] = idx >> 1;
    g_rowmap[idx] = r;
}

__global__ void __launch_bounds__(256) k_gather()
{
    const int row = blockIdx.x;
    if (row >= g_seg[NEXPERT]) return;
    int e = 0;
    while (g_seg[e + 1] <= row) e++;
    __half2* dst = reinterpret_cast<__half2*>(g_Xgh + (size_t)row * DMODEL);
    const int c = threadIdx.x * 4;
    if (row >= g_cur[e]) {   // padding row -> zero
        dst[threadIdx.x * 2]     = __floats2half2_rn(0.f, 0.f);
        dst[threadIdx.x * 2 + 1] = __floats2half2_rn(0.f, 0.f);
        return;
    }
    const float4 v = *reinterpret_cast<const float4*>(
        g_hn + (size_t)g_tok[row] * DMODEL + c);
    dst[threadIdx.x * 2]     = __floats2half2_rn(v.x, v.y);
    dst[threadIdx.x * 2 + 1] = __floats2half2_rn(v.z, v.w);
}

__global__ void __launch_bounds__(256) k_combine(float* __restrict__ out)
{
    const int t = blockIdx.x;
    const int r0 = g_rowmap[t * 2], r1 = g_rowmap[t * 2 + 1];
    const float w0 = g_wts[t * 2], w1 = g_wts[t * 2 + 1];
    const int c = threadIdx.x * 4;
    float4 a = *reinterpret_cast<const float4*>(g_h2 + (size_t)t * DMODEL + c);
    float4 y0 = *reinterpret_cast<const float4*>(g_Y + (size_t)r0 * DMODEL + c);
    float4 y1 = *reinterpret_cast<const float4*>(g_Y + (size_t)r1 * DMODEL + c);
    a.x += w0 * y0.x + w1 * y1.x;
    a.y += w0 * y0.y + w1 * y1.y;
    a.z += w0 * y0.z + w1 * y1.z;
    a.w += w0 * y0.w + w1 * y1.w;
    *reinterpret_cast<float4*>(out + (size_t)t * DMODEL + c) = a;
}

// ---------------- launch ----------------
extern "C" void kernel_launch(void* const* d_in, const int* in_sizes, int n_in,
                              void* d_out, int out_size)
{
    const float* x          = (const float*)d_in[0];
    const float* rms1_w     = (const float*)d_in[1];
    const float* rms2_w     = (const float*)d_in[2];
    const float* in_proj_w  = (const float*)d_in[3];
    const float* conv_w     = (const float*)d_in[4];
    const float* conv_b     = (const float*)d_in[5];
    const float* x_proj_w   = (const float*)d_in[6];
    const float* dt_proj_w  = (const float*)d_in[7];
    const float* dt_proj_b  = (const float*)d_in[8];
    const float* A_log      = (const float*)d_in[9];
    const float* D_skip     = (const float*)d_in[10];
    const float* out_proj_w = (const float*)d_in[11];
    const float* router_w   = (const float*)d_in[12];
    const float* Wg         = (const float*)d_in[13];
    const float* Wu         = (const float*)d_in[14];
    const float* Wd         = (const float*)d_in[15];
    float* out = (float*)d_out;

    cudaFuncSetAttribute(k_hgemm, cudaFuncAttributeMaxDynamicSharedMemorySize, H_SMEM);

    float *p_dbc, *p_part, *p_delta, *p_h2, *p_hn, *p_Y;
    __half *p_h1h, *p_xzh, *p_xich, *p_dbch, *p_y2h, *p_Xgh, *p_Gh0, *p_Gh;
    __half *p_ipwh, *p_xpwh, *p_dtwh, *p_opwh, *p_Wgh, *p_Wuh, *p_Wdh;
    cudaGetSymbolAddress((void**)&p_dbc, g_dbc);
    cudaGetSymbolAddress((void**)&p_part, g_part);
    cudaGetSymbolAddress((void**)&p_delta, g_delta);
    cudaGetSymbolAddress((void**)&p_h2, g_h2);
    cudaGetSymbolAddress((void**)&p_hn, g_hn);
    cudaGetSymbolAddress((void**)&p_Y, g_Y);
    cudaGetSymbolAddress((void**)&p_h1h, g_h1h);
    cudaGetSymbolAddress((void**)&p_xzh, g_xzh);
    cudaGetSymbolAddress((void**)&p_xich, g_xich);
    cudaGetSymbolAddress((void**)&p_dbch, g_dbch);
    cudaGetSymbolAddress((void**)&p_y2h, g_y2h);
    cudaGetSymbolAddress((void**)&p_Xgh, g_Xgh);
    cudaGetSymbolAddress((void**)&p_Gh0, g_Gh0);
    cudaGetSymbolAddress((void**)&p_Gh, g_Gh);
    cudaGetSymbolAddress((void**)&p_ipwh, g_ipwh);
    cudaGetSymbolAddress((void**)&p_xpwh, g_xpwh);
    cudaGetSymbolAddress((void**)&p_dtwh, g_dtwh);
    cudaGetSymbolAddress((void**)&p_opwh, g_opwh);
    cudaGetSymbolAddress((void**)&p_Wgh, g_Wgh);
    cudaGetSymbolAddress((void**)&p_Wuh, g_Wuh);
    cudaGetSymbolAddress((void**)&p_Wdh, g_Wdh);

    // ---- fork: MoE weight converts on a side stream (independent branch) ----
    cudaStream_t s2;
    cudaStreamCreateWithFlags(&s2, cudaStreamNonBlocking);
    cudaEvent_t evFork, evJoin;
    cudaEventCreateWithFlags(&evFork, cudaEventDisableTiming);
    cudaEventCreateWithFlags(&evJoin, cudaEventDisableTiming);
    cudaEventRecord(evFork, 0);
    cudaStreamWaitEvent(s2, evFork, 0);
    k_cvt<<<NEXPERT * 1024 * 4096 / 4096, 256, 0, s2>>>(Wg, p_Wgh, NEXPERT * 1024 * 4096 / 4);
    k_cvt<<<NEXPERT * 1024 * 4096 / 4096, 256, 0, s2>>>(Wu, p_Wuh, NEXPERT * 1024 * 4096 / 4);
    k_cvt<<<NEXPERT * 4096 * 1024 / 4096, 256, 0, s2>>>(Wd, p_Wdh, NEXPERT * 4096 * 1024 / 4);
    cudaEventRecord(evJoin, s2);

    // ---- main chain (default stream) ----
    // small weight converts + rmsnorm
    k_cvt<<<1024 * 4096 / 4096, 256>>>(in_proj_w, p_ipwh, 1024 * 4096 / 4);
    k_cvtpad<<<DINNER * LDDBC / 256, 256>>>(x_proj_w, p_xpwh);
    k_cvt<<<64 * 2048 / 4096, 256>>>(dt_proj_w, p_dtwh, 64 * 2048 / 4);
    k_cvt<<<2048 * 1024 / 4096, 256>>>(out_proj_w, p_opwh, 2048 * 1024 / 4);
    k_rmsnorm<<<TT, 256>>>(x, rms1_w, nullptr, p_h1h);
    // in_proj: [TT,1024]@[1024,4096] -> fp16 xz
    k_hgemm<<<dim3(32, 32), 256, H_SMEM>>>(
        p_h1h, p_ipwh, nullptr, p_xzh, DMODEL, DMODEL, 2 * DINNER, 2 * DINNER,
        0, nullptr, 1, 0, 0);
    // depthwise conv + silu (fp16)
    k_conv<<<TT * DINNER / 256, 256>>>(conv_w, conv_b);
    // x_proj split-K: [TT,2048]@[2048,128], 8 K-slices of 256 -> partials
    k_hgemm<<<dim3(1, 32, KSPL), 256, H_SMEM>>>(
        p_xich, p_xpwh, p_part, nullptr, DINNER / KSPL, DINNER, LDDBC, LDDBC,
        0, nullptr, 0, 0, (size_t)TT * LDDBC);
    // reduce partials -> fp32 dbc + fp16 dbch
    k_red8<<<TT * LDDBC / 256, 256>>>();
    // dt_proj + softplus: [TT,64] @ [64,2048] -> fp32 delta
    k_hgemm<<<dim3(16, 32), 256, H_SMEM>>>(
        p_dbch, p_dtwh, p_delta, nullptr, DTRANK, LDDBC, DINNER, DINNER,
        2, dt_proj_b, 0, 0, 0);
    // selective scan + gating -> fp16 y2h
    k_scan<<<NBATCH * (DINNER / 16), 256>>>(A_log, D_skip);
    // out_proj + residual: [TT,2048] @ [2048,1024] + x -> fp32 h2
    k_hgemm<<<dim3(8, 32), 256, H_SMEM>>>(
        p_y2h, p_opwh, p_h2, nullptr, DINNER, DINNER, DMODEL, DMODEL,
        1, x, 0, 0, 0);
    // rmsnorm2 fused with router (needs g_cnt zeroed first)
    k_zero8<<<1, 32>>>();
    k_rms_router<<<TT, 256>>>(p_h2, rms2_w, p_hn, router_w);
    k_seg<<<1, 1>>>();
    k_assign<<<TT * 2 / 256, 256>>>();
    k_gather<<<MAXR, 256>>>();

    // ---- join: MoE weights must be converted before the grouped GEMMs ----
    cudaStreamWaitEvent(0, evJoin, 0);

    // MoE grouped GEMMs (gate fp16 end-to-end; GLU fused via mode 4)
    k_hgemm<<<dim3(FFND / 128, MAXR / 128), 256, H_SMEM>>>(
        p_Xgh, p_Wgh, nullptr, p_Gh0, DMODEL, DMODEL, FFND, FFND,
        0, nullptr, 1, 1, (size_t)DMODEL * FFND);
    k_hgemm<<<dim3(FFND / 128, MAXR / 128), 256, H_SMEM>>>(
        p_Xgh, p_Wuh, nullptr, p_Gh, DMODEL, DMODEL, FFND, FFND,
        4, p_Gh0, 1, 1, (size_t)DMODEL * FFND);
    k_hgemm<<<dim3(DMODEL / 128, MAXR / 128), 256, H_SMEM>>>(
        p_Gh, p_Wdh, p_Y, nullptr, FFND, FFND, DMODEL, DMODEL,
        0, nullptr, 0, 1, (size_t)FFND * DMODEL);
    // combine + residual -> out
    k_combine<<<TT, 256>>>(out);
}

// round 15
// speedup vs baseline: 1.0470x; 1.0470x over previous
#include <cuda_runtime.h>
#include <cuda_fp16.h>
#include <math.h>
#include <stdint.h>

// ---------------- problem constants ----------------
#define NBATCH   2
#define LSEQ     2048
#define TT       4096            // NBATCH*LSEQ tokens
#define DMODEL   1024
#define DINNER   2048
#define DSTATE   16
#define DTRANK   64
#define NEXPERT  8
#define FFND     4096
#define LDDBC    128             // padded DT_RANK + 2*D_STATE (96 -> 128)
#define MAXR     9216            // 2*TT + 8*128 padding headroom (multiple of 128)

// ---------------- scratch (device globals; no allocation allowed) ----------
// fp32 buffers (scan recurrence / residual path)
__device__ float g_dbc[(size_t)TT * LDDBC];
__device__ float g_delta[(size_t)TT * DINNER];
__device__ float g_h2 [(size_t)TT * DMODEL];
__device__ float g_hn [(size_t)TT * DMODEL];
__device__ float g_Y  [(size_t)MAXR * DMODEL];
// fp16 activation buffers
__device__ __half g_h1h [(size_t)TT * DMODEL];
__device__ __half g_xzh [(size_t)TT * 2 * DINNER];
__device__ __half g_xich[(size_t)TT * DINNER];
__device__ __half g_dbch[(size_t)TT * LDDBC];
__device__ __half g_y2h [(size_t)TT * DINNER];
__device__ __half g_Xgh [(size_t)MAXR * DMODEL];
__device__ __half g_Gh0 [(size_t)MAXR * FFND];   // gate (pre-silu)
__device__ __half g_Gh  [(size_t)MAXR * FFND];   // silu(gate)*up
// fp16 weights, ORIGINAL [K][N] layout (B operands via ldmatrix.trans)
__device__ __half g_ipwh[(size_t)DMODEL * (2 * DINNER)];
__device__ __half g_xpwh[(size_t)DINNER * LDDBC];        // padded cols 96->128
__device__ __half g_dtwh[(size_t)DTRANK * DINNER];
__device__ __half g_opwh[(size_t)DINNER * DMODEL];
__device__ __half g_Wgh [(size_t)NEXPERT * DMODEL * FFND];
__device__ __half g_Wuh [(size_t)NEXPERT * DMODEL * FFND];
__device__ __half g_Wdh [(size_t)NEXPERT * FFND * DMODEL];
// MoE routing
__device__ int   g_sel[TT * 2];
__device__ float g_wts[TT * 2];
__device__ int   g_cnt[NEXPERT];
__device__ int   g_cur[NEXPERT];
__device__ int   g_seg[NEXPERT + 1];
__device__ int   g_tok[MAXR];
__device__ int   g_rowmap[TT * 2];

// ---------------- helpers ----------------
__device__ __forceinline__ float siluf(float x) { return x / (1.0f + __expf(-x)); }
__device__ __forceinline__ float softplusf(float x) {
    return (x > 20.0f) ? x : log1pf(__expf(x));
}
__device__ __forceinline__ void cp16(uint32_t sdst, const void* g) {
    asm volatile("cp.async.cg.shared.global [%0], [%1], 16;" :: "r"(sdst), "l"(g));
}
__device__ __forceinline__ void ldsm_x4(unsigned* r, uint32_t saddr) {
    asm volatile(
        "ldmatrix.sync.aligned.m8n8.x4.shared.b16 {%0,%1,%2,%3}, [%4];\n"
        : "=r"(r[0]), "=r"(r[1]), "=r"(r[2]), "=r"(r[3]) : "r"(saddr));
}
__device__ __forceinline__ void ldsm_x4t(unsigned* r, uint32_t saddr) {
    asm volatile(
        "ldmatrix.sync.aligned.m8n8.x4.trans.shared.b16 {%0,%1,%2,%3}, [%4];\n"
        : "=r"(r[0]), "=r"(r[1]), "=r"(r[2]), "=r"(r[3]) : "r"(saddr));
}
__device__ __forceinline__ void mma_f16(float* c, const unsigned* a, const unsigned* b) {
    asm volatile(
        "mma.sync.aligned.m16n8k16.row.col.f32.f16.f16.f32 "
        "{%0,%1,%2,%3},{%4,%5,%6,%7},{%8,%9},{%0,%1,%2,%3};\n"
        : "+f"(c[0]), "+f"(c[1]), "+f"(c[2]), "+f"(c[3])
        : "r"(a[0]), "r"(a[1]), "r"(a[2]), "r"(a[3]), "r"(b[0]), "r"(b[1]));
}

// ---------------- rmsnorm: one block per row; fp32 or fp16 out ----------------
__global__ void __launch_bounds__(256) k_rmsnorm(const float* __restrict__ x,
                                                 const float* __restrict__ w,
                                                 float* __restrict__ o,
                                                 __half* __restrict__ oh)
{
    __shared__ float red[8];
    const int r = blockIdx.x, tid = threadIdx.x;
    const float* xr = x + (size_t)r * DMODEL;
    float s = 0.f;
    #pragma unroll
    for (int i = 0; i < DMODEL / 256; i++) {
        float v = xr[tid + i * 256];
        s += v * v;
    }
    #pragma unroll
    for (int off = 16; off; off >>= 1) s += __shfl_xor_sync(0xffffffff, s, off);
    if ((tid & 31) == 0) red[tid >> 5] = s;
    __syncthreads();
    if (tid < 8) {
        float v = red[tid];
        #pragma unroll
        for (int off = 4; off; off >>= 1) v += __shfl_xor_sync(0xff, v, off);
        if (tid == 0) red[0] = v;
    }
    __syncthreads();
    const float rms = rsqrtf(red[0] * (1.0f / DMODEL) + 1e-5f);
    #pragma unroll
    for (int i = 0; i < DMODEL / 256; i++) {
        const int c = tid + i * 256;
        const float v = xr[c] * rms * w[c];
        if (oh) oh[(size_t)r * DMODEL + c] = __float2half(v);
        else    o [(size_t)r * DMODEL + c] = v;
    }
}

// ---------------- fused rmsnorm2 + router (one block per token) --------------
__global__ void __launch_bounds__(256) k_rms_router(const float* __restrict__ x,
                                                    const float* __restrict__ w,
                                                    float* __restrict__ o,
                                                    const float* __restrict__ rw)
{
    __shared__ float red[8];
    __shared__ float sred[8][NEXPERT];
    const int r = blockIdx.x, tid = threadIdx.x;
    const int warp = tid >> 5, lane = tid & 31;
    const float* xr = x + (size_t)r * DMODEL;
    float s = 0.f;
    #pragma unroll
    for (int i = 0; i < DMODEL / 256; i++) {
        float v = xr[tid + i * 256];
        s += v * v;
    }
    #pragma unroll
    for (int off = 16; off; off >>= 1) s += __shfl_xor_sync(0xffffffff, s, off);
    if (lane == 0) red[warp] = s;
    __syncthreads();
    if (tid < 8) {
        float v = red[tid];
        #pragma unroll
        for (int off = 4; off; off >>= 1) v += __shfl_xor_sync(0xff, v, off);
        if (tid == 0) red[0] = v;
    }
    __syncthreads();
    const float rms = rsqrtf(red[0] * (1.0f / DMODEL) + 1e-5f);

    float lg[NEXPERT];
    #pragma unroll
    for (int e = 0; e < NEXPERT; e++) lg[e] = 0.f;
    #pragma unroll
    for (int i = 0; i < DMODEL / 256; i++) {
        const int c = tid + i * 256;
        const float v = xr[c] * rms * w[c];
        o[(size_t)r * DMODEL + c] = v;
        #pragma unroll
        for (int e = 0; e < NEXPERT; e++) lg[e] += v * rw[c * NEXPERT + e];
    }
    #pragma unroll
    for (int off = 16; off; off >>= 1)
        #pragma unroll
        for (int e = 0; e < NEXPERT; e++)
            lg[e] += __shfl_xor_sync(0xffffffff, lg[e], off);
    if (lane == 0)
        #pragma unroll
        for (int e = 0; e < NEXPERT; e++) sred[warp][e] = lg[e];
    __syncthreads();
    if (tid == 0) {
        float p[NEXPERT];
        #pragma unroll
        for (int e = 0; e < NEXPERT; e++) {
            float a = 0.f;
            #pragma unroll
            for (int wgi = 0; wgi < 8; wgi++) a += sred[wgi][e];
            p[e] = a;
        }
        float m = p[0];
        #pragma unroll
        for (int e = 1; e < NEXPERT; e++) m = fmaxf(m, p[e]);
        float sum = 0.f;
        #pragma unroll
        for (int e = 0; e < NEXPERT; e++) { p[e] = __expf(p[e] - m); sum += p[e]; }
        const float inv = 1.0f / sum;
        #pragma unroll
        for (int e = 0; e < NEXPERT; e++) p[e] *= inv;
        int i1 = 0;
        #pragma unroll
        for (int e = 1; e < NEXPERT; e++) if (p[e] > p[i1]) i1 = e;
        int i2 = (i1 == 0) ? 1 : 0;
        #pragma unroll
        for (int e = 0; e < NEXPERT; e++) if (e != i1 && p[e] > p[i2]) i2 = e;
        g_sel[r * 2] = i1; g_sel[r * 2 + 1] = i2;
        g_wts[r * 2] = p[i1]; g_wts[r * 2 + 1] = p[i2];
        atomicAdd(&g_cnt[i1], 1);
        atomicAdd(&g_cnt[i2], 1);
    }
}

// ---------------- coalesced fp32 -> fp16 convert, MLP=4 per thread ------------
__global__ void __launch_bounds__(256) k_cvt(const float* __restrict__ in,
                                             __half* __restrict__ out, int n4)
{
    const int base = blockIdx.x * 1024 + threadIdx.x;
    float4 v[4];
    #pragma unroll
    for (int j = 0; j < 4; j++)
        v[j] = reinterpret_cast<const float4*>(in)[base + j * 256];
    #pragma unroll
    for (int j = 0; j < 4; j++) {
        __half2* o = reinterpret_cast<__half2*>(out) + (size_t)(base + j * 256) * 2;
        o[0] = __floats2half2_rn(v[j].x, v[j].y);
        o[1] = __floats2half2_rn(v[j].z, v[j].w);
    }
}

// x_proj weight: [2048][96] fp32 -> [2048][128] fp16 (pad cols with 0)
__global__ void __launch_bounds__(256) k_cvtpad(const float* __restrict__ in,
                                                __half* __restrict__ out)
{
    const int i = blockIdx.x * 256 + threadIdx.x;   // over DINNER*128
    const int k = i >> 7, n = i & 127;
    out[i] = __float2half((n < 96) ? in[k * 96 + n] : 0.f);
}

// ---------------- fp16 tensor-core GEMM: C[M,N] = A[M,K] @ B[K,N] --------------
// A fp16 [M][K] row-major; B fp16 [K][N] row-major (fragments via ldmatrix.trans).
// 128x128x64 tiles, 8 warps (64x32 warp tiles), cp.async 3-stage pipeline.
// mode 0: plain; 1: +aux32[row*ldc+col]; 2: softplus(acc+aux32[col]);
// mode 4: silu(aux16[row*ldc+col]) * acc.
// outKind 0: fp32 C; 1: fp16 Ch; 2: both.
#define TK     64
#define NSTG   3
#define ASTR   144                 // bytes per A smem row (64 halves + 8 pad)
#define BSTR   272                 // bytes per B smem row (128 halves + 8 pad)
#define ASTG   (128 * ASTR)        // 18432
#define BSTG   (TK * BSTR)         // 17408
#define H_SMEM (NSTG * (ASTG + BSTG)) // 107520

__global__ void __launch_bounds__(256, 2)
k_hgemm(const __half* __restrict__ A, const __half* __restrict__ Bbase,
        float* __restrict__ C, __half* __restrict__ Ch,
        int K, int lda, int ldb, int ldc,
        int mode, const void* __restrict__ aux, int outKind,
        int grouped, size_t expStride)
{
    const int m0 = blockIdx.y * 128;
    const int n0 = blockIdx.x * 128;
    const __half* B = Bbase;
    if (grouped) {
        if (m0 >= g_seg[NEXPERT]) return;
        int e = 0;
        while (g_seg[e + 1] <= m0) e++;
        B += (size_t)e * expStride;
    }

    extern __shared__ __align__(16) char hsm[];
    const uint32_t sb = (uint32_t)__cvta_generic_to_shared(hsm);
    const uint32_t sbB = sb + NSTG * ASTG;

    const int tid = threadIdx.x;
    const int wid = tid >> 5, lane = tid & 31;
    const int wm = (wid >> 2) * 64;
    const int wn = (wid & 3) * 32;
    const int lr = lane >> 2, lc = lane & 3;      // epilogue coords
    const int q = lane >> 3, r8 = lane & 7;       // ldmatrix quadrant coords

    const uint32_t aoff = (uint32_t)((wm + ((q & 1) << 3) + r8) * ASTR + ((q >> 1) << 4));
    const uint32_t boff = (uint32_t)((((q & 1) << 3) + r8) * BSTR + ((wn + ((q >> 1) << 3)) << 1));

    float acc[4][4][4];
    #pragma unroll
    for (int i = 0; i < 4; i++)
        #pragma unroll
        for (int j = 0; j < 4; j++)
            #pragma unroll
            for (int v = 0; v < 4; v++) acc[i][j][v] = 0.f;

    const int nIter = K / TK;

    auto issue = [&](int st, int k0) {
        #pragma unroll
        for (int w = 0; w < 4; w++) {       // A: 128 rows x 8 chunks
            const int id = tid + w * 256;
            const int row = id >> 3, ch = id & 7;
            cp16(sb + st * ASTG + row * ASTR + ch * 16,
                 A + (size_t)(m0 + row) * lda + k0 + ch * 8);
        }
        #pragma unroll
        for (int w = 0; w < 4; w++) {       // B: 64 k-rows x 16 chunks
            const int id = tid + w * 256;
            const int kr = id >> 4, ch = id & 15;
            cp16(sbB + st * BSTG + kr * BSTR + ch * 16,
                 B + (size_t)(k0 + kr) * ldb + n0 + ch * 8);
        }
        asm volatile("cp.async.commit_group;" ::: "memory");
    };

    issue(0, 0);
    if (nIter > 1) issue(1, TK);

    for (int it = 0; it < nIter; it++) {
        if (it + 2 < nIter) issue((it + 2) % NSTG, (it + 2) * TK);
        if (it + 3 <= nIter) {
            asm volatile("cp.async.wait_group 2;" ::: "memory");
        } else if (it + 2 <= nIter) {
            asm volatile("cp.async.wait_group 1;" ::: "memory");
        } else {
            asm volatile("cp.async.wait_group 0;" ::: "memory");
        }
        __syncthreads();

        const int st = it % NSTG;
        const uint32_t aBase = sb + st * ASTG + aoff;
        const uint32_t bBase = sbB + st * BSTG + boff;
        #pragma unroll
        for (int ks = 0; ks < 4; ks++) {
            unsigned a[4][4], bt[2][4];
            #pragma unroll
            for (int mt = 0; mt < 4; mt++)
                ldsm_x4(a[mt], aBase + mt * (16 * ASTR) + ks * 32);
            #pragma unroll
            for (int g = 0; g < 2; g++)
                ldsm_x4t(bt[g], bBase + ks * (16 * BSTR) + g * 32);
            #pragma unroll
            for (int mt = 0; mt < 4; mt++)
                #pragma unroll
                for (int nt = 0; nt < 4; nt++)
                    mma_f16(acc[mt][nt], a[mt], &bt[nt >> 1][(nt & 1) * 2]);
        }
        __syncthreads();
    }

    // epilogue
    const float* aux32 = (const float*)aux;
    const __half* aux16 = (const __half*)aux;
    #pragma unroll
    for (int mt = 0; mt < 4; mt++) {
        #pragma unroll
        for (int nt = 0; nt < 4; nt++) {
            const int row = m0 + wm + mt * 16 + lr;
            const int col = n0 + wn + nt * 8 + lc * 2;
            float2 v0 = make_float2(acc[mt][nt][0], acc[mt][nt][1]);   // row
            float2 v1 = make_float2(acc[mt][nt][2], acc[mt][nt][3]);   // row+8
            if (mode == 1) {
                const float2 r0 = *reinterpret_cast<const float2*>(aux32 + (size_t)row * ldc + col);
                const float2 r1 = *reinterpret_cast<const float2*>(aux32 + (size_t)(row + 8) * ldc + col);
                v0.x += r0.x; v0.y += r0.y;
                v1.x += r1.x; v1.y += r1.y;
            } else if (mode == 2) {
                const float b0 = aux32[col], b1 = aux32[col + 1];
                v0.x = softplusf(v0.x + b0); v0.y = softplusf(v0.y + b1);
                v1.x = softplusf(v1.x + b0); v1.y = softplusf(v1.y + b1);
            } else if (mode == 4) {
                const float2 g0 = __half22float2(
                    *reinterpret_cast<const __half2*>(aux16 + (size_t)row * ldc + col));
                const float2 g1 = __half22float2(
                    *reinterpret_cast<const __half2*>(aux16 + (size_t)(row + 8) * ldc + col));
                v0.x *= siluf(g0.x); v0.y *= siluf(g0.y);
                v1.x *= siluf(g1.x); v1.y *= siluf(g1.y);
            }
            if (outKind != 1) {
                *reinterpret_cast<float2*>(C + (size_t)row * ldc + col) = v0;
                *reinterpret_cast<float2*>(C + (size_t)(row + 8) * ldc + col) = v1;
            }
            if (outKind >= 1) {
                *reinterpret_cast<__half2*>(Ch + (size_t)row * ldc + col) =
                    __floats2half2_rn(v0.x, v0.y);
                *reinterpret_cast<__half2*>(Ch + (size_t)(row + 8) * ldc + col) =
                    __floats2half2_rn(v1.x, v1.y);
            }
        }
    }
}

// ---------------- causal depthwise conv + silu (2 channels/thread, half2) ----
__global__ void __launch_bounds__(256) k_conv(const float* __restrict__ cw,
                                              const float* __restrict__ cb)
{
    const int idx = blockIdx.x * 256 + threadIdx.x;   // over TT*DINNER/2
    const int cp = idx & (DINNER / 2 - 1);            // channel pair
    const int c = cp * 2;
    const int tg = idx / (DINNER / 2);                 // token index
    const int l = tg & (LSEQ - 1);
    float a0 = cb[c], a1 = cb[c + 1];
    #pragma unroll
    for (int k = 0; k < 4; k++) {
        const int dl = l - 3 + k;
        if (dl >= 0) {
            const float2 xv = __half22float2(*reinterpret_cast<const __half2*>(
                g_xzh + (size_t)(tg - 3 + k) * (2 * DINNER) + c));
            a0 += cw[c * 4 + k] * xv.x;
            a1 += cw[(c + 1) * 4 + k] * xv.y;
        }
    }
    *reinterpret_cast<__half2*>(g_xich + (size_t)tg * DINNER + c) =
        __floats2half2_rn(siluf(a0), siluf(a1));
}

// ---------------- selective scan: 16 channels/block, 16 lanes/channel --------
__global__ void __launch_bounds__(256) k_scan(const float* __restrict__ A_log,
                                              const float* __restrict__ D_skip)
{
    const int b = blockIdx.x >> 7;               // batch
    const int cg = blockIdx.x & 127;             // channel group
    const int tid = threadIdx.x;
    const int c = cg * 16 + (tid >> 4);
    const int n = tid & 15;

    const float A = -__expf(A_log[c * DSTATE + n]);
    const float D = D_skip[c];
    float h = 0.f;

    const float*  dlt = g_delta + (size_t)b * LSEQ * DINNER + c;
    const __half* xin = g_xich  + (size_t)b * LSEQ * DINNER + c;
    const float*  dbc = g_dbc   + (size_t)b * LSEQ * LDDBC;
    const __half* zin = g_xzh   + (size_t)b * LSEQ * (2 * DINNER) + DINNER + c;
    __half* yout = g_y2h + (size_t)b * LSEQ * DINNER + c;

    for (int l = 0; l < LSEQ; l++) {
        const float d  = dlt[(size_t)l * DINNER];
        const float x  = __half2float(xin[(size_t)l * DINNER]);
        const float Bn = dbc[(size_t)l * LDDBC + DTRANK + n];
        const float Cn = dbc[(size_t)l * LDDBC + DTRANK + DSTATE + n];
        const float dA = __expf(d * A);
        h = dA * h + (d * x) * Bn;
        float v = h * Cn;
        v += __shfl_xor_sync(0xffffffff, v, 1);
        v += __shfl_xor_sync(0xffffffff, v, 2);
        v += __shfl_xor_sync(0xffffffff, v, 4);
        v += __shfl_xor_sync(0xffffffff, v, 8);
        if (n == 0) {
            const float z = __half2float(zin[(size_t)l * (2 * DINNER)]);
            yout[(size_t)l * DINNER] = __float2half((v + D * x) * siluf(z));
        }
    }
}

// ---------------- MoE bookkeeping ----------------
__global__ void k_zero8() { if (threadIdx.x < NEXPERT) g_cnt[threadIdx.x] = 0; }

__global__ void k_seg()
{
    int s = 0;
    g_seg[0] = 0;
    for (int e = 0; e < NEXPERT; e++) {
        g_cur[e] = s;
        s += ((g_cnt[e] + 127) / 128) * 128;
        g_seg[e + 1] = s;
    }
}

__global__ void __launch_bounds__(256) k_assign()
{
    const int idx = blockIdx.x * 256 + threadIdx.x;   // over TT*2
    const int e = g_sel[idx];
    const int r = atomicAdd(&g_cur[e], 1);
    g_tok[r] = idx >> 1;
    g_rowmap[idx] = r;
}

__global__ void __launch_bounds__(256) k_gather()
{
    const int row = blockIdx.x;
    if (row >= g_seg[NEXPERT]) return;
    int e = 0;
    while (g_seg[e + 1] <= row) e++;
    __half2* dst = reinterpret_cast<__half2*>(g_Xgh + (size_t)row * DMODEL);
    const int c = threadIdx.x * 4;
    if (row >= g_cur[e]) {   // padding row -> zero
        dst[threadIdx.x * 2]     = __floats2half2_rn(0.f, 0.f);
        dst[threadIdx.x * 2 + 1] = __floats2half2_rn(0.f, 0.f);
        return;
    }
    const float4 v = *reinterpret_cast<const float4*>(
        g_hn + (size_t)g_tok[row] * DMODEL + c);
    dst[threadIdx.x * 2]     = __floats2half2_rn(v.x, v.y);
    dst[threadIdx.x * 2 + 1] = __floats2half2_rn(v.z, v.w);
}

__global__ void __launch_bounds__(256) k_combine(float* __restrict__ out)
{
    const int t = blockIdx.x;
    const int r0 = g_rowmap[t * 2], r1 = g_rowmap[t * 2 + 1];
    const float w0 = g_wts[t * 2], w1 = g_wts[t * 2 + 1];
    const int c = threadIdx.x * 4;
    float4 a = *reinterpret_cast<const float4*>(g_h2 + (size_t)t * DMODEL + c);
    float4 y0 = *reinterpret_cast<const float4*>(g_Y + (size_t)r0 * DMODEL + c);
    float4 y1 = *reinterpret_cast<const float4*>(g_Y + (size_t)r1 * DMODEL + c);
    a.x += w0 * y0.x + w1 * y1.x;
    a.y += w0 * y0.y + w1 * y1.y;
    a.z += w0 * y0.z + w1 * y1.z;
    a.w += w0 * y0.w + w1 * y1.w;
    *reinterpret_cast<float4*>(out + (size_t)t * DMODEL + c) = a;
}

// ---------------- launch ----------------
extern "C" void kernel_launch(void* const* d_in, const int* in_sizes, int n_in,
                              void* d_out, int out_size)
{
    const float* x          = (const float*)d_in[0];
    const float* rms1_w     = (const float*)d_in[1];
    const float* rms2_w     = (const float*)d_in[2];
    const float* in_proj_w  = (const float*)d_in[3];
    const float* conv_w     = (const float*)d_in[4];
    const float* conv_b     = (const float*)d_in[5];
    const float* x_proj_w   = (const float*)d_in[6];
    const float* dt_proj_w  = (const float*)d_in[7];
    const float* dt_proj_b  = (const float*)d_in[8];
    const float* A_log      = (const float*)d_in[9];
    const float* D_skip     = (const float*)d_in[10];
    const float* out_proj_w = (const float*)d_in[11];
    const float* router_w   = (const float*)d_in[12];
    const float* Wg         = (const float*)d_in[13];
    const float* Wu         = (const float*)d_in[14];
    const float* Wd         = (const float*)d_in[15];
    float* out = (float*)d_out;

    cudaFuncSetAttribute(k_hgemm, cudaFuncAttributeMaxDynamicSharedMemorySize, H_SMEM);

    float *p_dbc, *p_delta, *p_h2, *p_hn, *p_Y;
    __half *p_h1h, *p_xzh, *p_xich, *p_dbch, *p_y2h, *p_Xgh, *p_Gh0, *p_Gh;
    __half *p_ipwh, *p_xpwh, *p_dtwh, *p_opwh, *p_Wgh, *p_Wuh, *p_Wdh;
    cudaGetSymbolAddress((void**)&p_dbc, g_dbc);
    cudaGetSymbolAddress((void**)&p_delta, g_delta);
    cudaGetSymbolAddress((void**)&p_h2, g_h2);
    cudaGetSymbolAddress((void**)&p_hn, g_hn);
    cudaGetSymbolAddress((void**)&p_Y, g_Y);
    cudaGetSymbolAddress((void**)&p_h1h, g_h1h);
    cudaGetSymbolAddress((void**)&p_xzh, g_xzh);
    cudaGetSymbolAddress((void**)&p_xich, g_xich);
    cudaGetSymbolAddress((void**)&p_dbch, g_dbch);
    cudaGetSymbolAddress((void**)&p_y2h, g_y2h);
    cudaGetSymbolAddress((void**)&p_Xgh, g_Xgh);
    cudaGetSymbolAddress((void**)&p_Gh0, g_Gh0);
    cudaGetSymbolAddress((void**)&p_Gh, g_Gh);
    cudaGetSymbolAddress((void**)&p_ipwh, g_ipwh);
    cudaGetSymbolAddress((void**)&p_xpwh, g_xpwh);
    cudaGetSymbolAddress((void**)&p_dtwh, g_dtwh);
    cudaGetSymbolAddress((void**)&p_opwh, g_opwh);
    cudaGetSymbolAddress((void**)&p_Wgh, g_Wgh);
    cudaGetSymbolAddress((void**)&p_Wuh, g_Wuh);
    cudaGetSymbolAddress((void**)&p_Wdh, g_Wdh);

    // ---- fork: MoE weight converts on a side stream (independent branch) ----
    cudaStream_t s2;
    cudaStreamCreateWithFlags(&s2, cudaStreamNonBlocking);
    cudaEvent_t evFork, evJoin;
    cudaEventCreateWithFlags(&evFork, cudaEventDisableTiming);
    cudaEventCreateWithFlags(&evJoin, cudaEventDisableTiming);
    cudaEventRecord(evFork, 0);
    cudaStreamWaitEvent(s2, evFork, 0);
    k_cvt<<<NEXPERT * 1024 * 4096 / 4096, 256, 0, s2>>>(Wg, p_Wgh, NEXPERT * 1024 * 4096 / 4);
    k_cvt<<<NEXPERT * 1024 * 4096 / 4096, 256, 0, s2>>>(Wu, p_Wuh, NEXPERT * 1024 * 4096 / 4);
    k_cvt<<<NEXPERT * 4096 * 1024 / 4096, 256, 0, s2>>>(Wd, p_Wdh, NEXPERT * 4096 * 1024 / 4);
    cudaEventRecord(evJoin, s2);

    // ---- main chain (default stream) ----
    // small weight converts + rmsnorm
    k_cvt<<<1024 * 4096 / 4096, 256>>>(in_proj_w, p_ipwh, 1024 * 4096 / 4);
    k_cvtpad<<<DINNER * LDDBC / 256, 256>>>(x_proj_w, p_xpwh);
    k_cvt<<<64 * 2048 / 4096, 256>>>(dt_proj_w, p_dtwh, 64 * 2048 / 4);
    k_cvt<<<2048 * 1024 / 4096, 256>>>(out_proj_w, p_opwh, 2048 * 1024 / 4);
    k_rmsnorm<<<TT, 256>>>(x, rms1_w, nullptr, p_h1h);
    // in_proj: [TT,1024]@[1024,4096] -> fp16 xz
    k_hgemm<<<dim3(32, 32), 256, H_SMEM>>>(
        p_h1h, p_ipwh, nullptr, p_xzh, DMODEL, DMODEL, 2 * DINNER, 2 * DINNER,
        0, nullptr, 1, 0, 0);
    // depthwise conv + silu (fp16, 2 channels/thread)
    k_conv<<<TT * DINNER / 512, 256>>>(conv_w, conv_b);
    // x_proj: [TT,2048] @ [2048,128] -> fp32 dbc + fp16 dbch
    k_hgemm<<<dim3(1, 32), 256, H_SMEM>>>(
        p_xich, p_xpwh, p_dbc, p_dbch, DINNER, DINNER, LDDBC, LDDBC,
        0, nullptr, 2, 0, 0);
    // dt_proj + softplus: [TT,64] @ [64,2048] -> fp32 delta
    k_hgemm<<<dim3(16, 32), 256, H_SMEM>>>(
        p_dbch, p_dtwh, p_delta, nullptr, DTRANK, LDDBC, DINNER, DINNER,
        2, dt_proj_b, 0, 0, 0);
    // selective scan + gating -> fp16 y2h
    k_scan<<<NBATCH * (DINNER / 16), 256>>>(A_log, D_skip);
    // out_proj + residual: [TT,2048] @ [2048,1024] + x -> fp32 h2
    k_hgemm<<<dim3(8, 32), 256, H_SMEM>>>(
        p_y2h, p_opwh, p_h2, nullptr, DINNER, DINNER, DMODEL, DMODEL,
        1, x, 0, 0, 0);
    // rmsnorm2 fused with router (needs g_cnt zeroed first)
    k_zero8<<<1, 32>>>();
    k_rms_router<<<TT, 256>>>(p_h2, rms2_w, p_hn, router_w);
    k_seg<<<1, 1>>>();
    k_assign<<<TT * 2 / 256, 256>>>();
    k_gather<<<MAXR, 256>>>();

    // ---- join: MoE weights must be converted before the grouped GEMMs ----
    cudaStreamWaitEvent(0, evJoin, 0);

    // MoE grouped GEMMs (gate fp16 end-to-end; GLU fused via mode 4)
    k_hgemm<<<dim3(FFND / 128, MAXR / 128), 256, H_SMEM>>>(
        p_Xgh, p_Wgh, nullptr, p_Gh0, DMODEL, DMODEL, FFND, FFND,
        0, nullptr, 1, 1, (size_t)DMODEL * FFND);
    k_hgemm<<<dim3(FFND / 128, MAXR / 128), 256, H_SMEM>>>(
        p_Xgh, p_Wuh, nullptr, p_Gh, DMODEL, DMODEL, FFND, FFND,
        4, p_Gh0, 1, 1, (size_t)DMODEL * FFND);
    k_hgemm<<<dim3(DMODEL / 128, MAXR / 128), 256, H_SMEM>>>(
        p_Gh, p_Wdh, p_Y, nullptr, FFND, FFND, DMODEL, DMODEL,
        0, nullptr, 0, 1, (size_t)FFND * DMODEL);
    // combine + residual -> out
    k_combine<<<TT, 256>>>(out);
}

// round 16
// speedup vs baseline: 1.0759x; 1.0276x over previous
#include <cuda_runtime.h>
#include <cuda_fp16.h>
#include <math.h>
#include <stdint.h>

// ---------------- problem constants ----------------
#define NBATCH   2
#define LSEQ     2048
#define TT       4096            // NBATCH*LSEQ tokens
#define DMODEL   1024
#define DINNER   2048
#define DSTATE   16
#define DTRANK   64
#define NEXPERT  8
#define FFND     4096
#define LDDBC    128             // padded DT_RANK + 2*D_STATE (96 -> 128)
#define MAXR     9216            // 2*TT + 8*128 padding headroom (multiple of 128)

// ---------------- scratch (device globals; no allocation allowed) ----------
// fp32 buffers (scan recurrence / residual path)
__device__ float g_dbc[(size_t)TT * LDDBC];
__device__ float g_delta[(size_t)TT * DINNER];
__device__ float g_h2 [(size_t)TT * DMODEL];
__device__ float g_hn [(size_t)TT * DMODEL];
__device__ float g_Y  [(size_t)MAXR * DMODEL];
// fp16 activation buffers
__device__ __half g_h1h [(size_t)TT * DMODEL];
__device__ __half g_xzh [(size_t)TT * 2 * DINNER];
__device__ __half g_xich[(size_t)TT * DINNER];
__device__ __half g_dbch[(size_t)TT * LDDBC];
__device__ __half g_y2h [(size_t)TT * DINNER];
__device__ __half g_Xgh [(size_t)MAXR * DMODEL];
__device__ __half g_Gh0 [(size_t)MAXR * FFND];   // gate (pre-silu)
__device__ __half g_Gh  [(size_t)MAXR * FFND];   // silu(gate)*up
// fp16 weights, ORIGINAL [K][N] layout (B operands via ldmatrix.trans)
__device__ __half g_ipwh[(size_t)DMODEL * (2 * DINNER)];
__device__ __half g_xpwh[(size_t)DINNER * LDDBC];        // padded cols 96->128
__device__ __half g_dtwh[(size_t)DTRANK * DINNER];
__device__ __half g_opwh[(size_t)DINNER * DMODEL];
__device__ __half g_Wgh [(size_t)NEXPERT * DMODEL * FFND];
__device__ __half g_Wuh [(size_t)NEXPERT * DMODEL * FFND];
__device__ __half g_Wdh [(size_t)NEXPERT * FFND * DMODEL];
// MoE routing
__device__ int   g_sel[TT * 2];
__device__ float g_wts[TT * 2];
__device__ int   g_cnt[NEXPERT];
__device__ int   g_cur[NEXPERT];
__device__ int   g_seg[NEXPERT + 1];
__device__ int   g_tok[MAXR];
__device__ int   g_rowmap[TT * 2];

// ---------------- helpers ----------------
__device__ __forceinline__ float siluf(float x) { return x / (1.0f + __expf(-x)); }
__device__ __forceinline__ float softplusf(float x) {
    return (x > 20.0f) ? x : log1pf(__expf(x));
}
__device__ __forceinline__ void cp16(uint32_t sdst, const void* g) {
    asm volatile("cp.async.cg.shared.global [%0], [%1], 16;" :: "r"(sdst), "l"(g));
}
__device__ __forceinline__ void ldsm_x4(unsigned* r, uint32_t saddr) {
    asm volatile(
        "ldmatrix.sync.aligned.m8n8.x4.shared.b16 {%0,%1,%2,%3}, [%4];\n"
        : "=r"(r[0]), "=r"(r[1]), "=r"(r[2]), "=r"(r[3]) : "r"(saddr));
}
__device__ __forceinline__ void ldsm_x4t(unsigned* r, uint32_t saddr) {
    asm volatile(
        "ldmatrix.sync.aligned.m8n8.x4.trans.shared.b16 {%0,%1,%2,%3}, [%4];\n"
        : "=r"(r[0]), "=r"(r[1]), "=r"(r[2]), "=r"(r[3]) : "r"(saddr));
}
__device__ __forceinline__ void mma_f16(float* c, const unsigned* a, const unsigned* b) {
    asm volatile(
        "mma.sync.aligned.m16n8k16.row.col.f32.f16.f16.f32 "
        "{%0,%1,%2,%3},{%4,%5,%6,%7},{%8,%9},{%0,%1,%2,%3};\n"
        : "+f"(c[0]), "+f"(c[1]), "+f"(c[2]), "+f"(c[3])
        : "r"(a[0]), "r"(a[1]), "r"(a[2]), "r"(a[3]), "r"(b[0]), "r"(b[1]));
}

// ---------------- rmsnorm: one block per row; fp32 or fp16 out ----------------
__global__ void __launch_bounds__(256) k_rmsnorm(const float* __restrict__ x,
                                                 const float* __restrict__ w,
                                                 float* __restrict__ o,
                                                 __half* __restrict__ oh)
{
    __shared__ float red[8];
    const int r = blockIdx.x, tid = threadIdx.x;
    const float* xr = x + (size_t)r * DMODEL;
    float s = 0.f;
    #pragma unroll
    for (int i = 0; i < DMODEL / 256; i++) {
        float v = xr[tid + i * 256];
        s += v * v;
    }
    #pragma unroll
    for (int off = 16; off; off >>= 1) s += __shfl_xor_sync(0xffffffff, s, off);
    if ((tid & 31) == 0) red[tid >> 5] = s;
    __syncthreads();
    if (tid < 8) {
        float v = red[tid];
        #pragma unroll
        for (int off = 4; off; off >>= 1) v += __shfl_xor_sync(0xff, v, off);
        if (tid == 0) red[0] = v;
    }
    __syncthreads();
    const float rms = rsqrtf(red[0] * (1.0f / DMODEL) + 1e-5f);
    #pragma unroll
    for (int i = 0; i < DMODEL / 256; i++) {
        const int c = tid + i * 256;
        const float v = xr[c] * rms * w[c];
        if (oh) oh[(size_t)r * DMODEL + c] = __float2half(v);
        else    o [(size_t)r * DMODEL + c] = v;
    }
}

// ---------------- fused rmsnorm2 + router (one block per token) --------------
__global__ void __launch_bounds__(256) k_rms_router(const float* __restrict__ x,
                                                    const float* __restrict__ w,
                                                    float* __restrict__ o,
                                                    const float* __restrict__ rw)
{
    __shared__ float red[8];
    __shared__ float sred[8][NEXPERT];
    const int r = blockIdx.x, tid = threadIdx.x;
    const int warp = tid >> 5, lane = tid & 31;
    const float* xr = x + (size_t)r * DMODEL;
    float s = 0.f;
    #pragma unroll
    for (int i = 0; i < DMODEL / 256; i++) {
        float v = xr[tid + i * 256];
        s += v * v;
    }
    #pragma unroll
    for (int off = 16; off; off >>= 1) s += __shfl_xor_sync(0xffffffff, s, off);
    if (lane == 0) red[warp] = s;
    __syncthreads();
    if (tid < 8) {
        float v = red[tid];
        #pragma unroll
        for (int off = 4; off; off >>= 1) v += __shfl_xor_sync(0xff, v, off);
        if (tid == 0) red[0] = v;
    }
    __syncthreads();
    const float rms = rsqrtf(red[0] * (1.0f / DMODEL) + 1e-5f);

    float lg[NEXPERT];
    #pragma unroll
    for (int e = 0; e < NEXPERT; e++) lg[e] = 0.f;
    #pragma unroll
    for (int i = 0; i < DMODEL / 256; i++) {
        const int c = tid + i * 256;
        const float v = xr[c] * rms * w[c];
        o[(size_t)r * DMODEL + c] = v;
        #pragma unroll
        for (int e = 0; e < NEXPERT; e++) lg[e] += v * rw[c * NEXPERT + e];
    }
    #pragma unroll
    for (int off = 16; off; off >>= 1)
        #pragma unroll
        for (int e = 0; e < NEXPERT; e++)
            lg[e] += __shfl_xor_sync(0xffffffff, lg[e], off);
    if (lane == 0)
        #pragma unroll
        for (int e = 0; e < NEXPERT; e++) sred[warp][e] = lg[e];
    __syncthreads();
    if (tid == 0) {
        float p[NEXPERT];
        #pragma unroll
        for (int e = 0; e < NEXPERT; e++) {
            float a = 0.f;
            #pragma unroll
            for (int wgi = 0; wgi < 8; wgi++) a += sred[wgi][e];
            p[e] = a;
        }
        float m = p[0];
        #pragma unroll
        for (int e = 1; e < NEXPERT; e++) m = fmaxf(m, p[e]);
        float sum = 0.f;
        #pragma unroll
        for (int e = 0; e < NEXPERT; e++) { p[e] = __expf(p[e] - m); sum += p[e]; }
        const float inv = 1.0f / sum;
        #pragma unroll
        for (int e = 0; e < NEXPERT; e++) p[e] *= inv;
        int i1 = 0;
        #pragma unroll
        for (int e = 1; e < NEXPERT; e++) if (p[e] > p[i1]) i1 = e;
        int i2 = (i1 == 0) ? 1 : 0;
        #pragma unroll
        for (int e = 0; e < NEXPERT; e++) if (e != i1 && p[e] > p[i2]) i2 = e;
        g_sel[r * 2] = i1; g_sel[r * 2 + 1] = i2;
        g_wts[r * 2] = p[i1]; g_wts[r * 2 + 1] = p[i2];
        atomicAdd(&g_cnt[i1], 1);
        atomicAdd(&g_cnt[i2], 1);
    }
}

// ---------------- coalesced fp32 -> fp16 convert, MLP=4 per thread ------------
__global__ void __launch_bounds__(256) k_cvt(const float* __restrict__ in,
                                             __half* __restrict__ out, int n4)
{
    const int base = blockIdx.x * 1024 + threadIdx.x;
    float4 v[4];
    #pragma unroll
    for (int j = 0; j < 4; j++)
        v[j] = reinterpret_cast<const float4*>(in)[base + j * 256];
    #pragma unroll
    for (int j = 0; j < 4; j++) {
        __half2* o = reinterpret_cast<__half2*>(out) + (size_t)(base + j * 256) * 2;
        o[0] = __floats2half2_rn(v[j].x, v[j].y);
        o[1] = __floats2half2_rn(v[j].z, v[j].w);
    }
}

// x_proj weight: [2048][96] fp32 -> [2048][128] fp16 (pad cols with 0)
__global__ void __launch_bounds__(256) k_cvtpad(const float* __restrict__ in,
                                                __half* __restrict__ out)
{
    const int i = blockIdx.x * 256 + threadIdx.x;   // over DINNER*128
    const int k = i >> 7, n = i & 127;
    out[i] = __float2half((n < 96) ? in[k * 96 + n] : 0.f);
}

// ---------------- fp16 tensor-core GEMM: C[M,N] = A[M,K] @ B[K,N] --------------
// A fp16 [M][K] row-major; B fp16 [K][N] row-major (fragments via ldmatrix.trans).
// 128x128x64 tiles, 8 warps (64x32 warp tiles), cp.async 3-stage pipeline.
// mode 0: plain; 1: +aux32[row*ldc+col]; 2: softplus(acc+aux32[col]);
// mode 4: silu(aux16[row*ldc+col]) * acc.
// outKind 0: fp32 C; 1: fp16 Ch; 2: both.
#define TK     64
#define NSTG   3
#define ASTR   144                 // bytes per A smem row (64 halves + 8 pad)
#define BSTR   272                 // bytes per B smem row (128 halves + 8 pad)
#define ASTG   (128 * ASTR)        // 18432
#define BSTG   (TK * BSTR)         // 17408
#define H_SMEM (NSTG * (ASTG + BSTG)) // 107520

__global__ void __launch_bounds__(256, 2)
k_hgemm(const __half* __restrict__ A, const __half* __restrict__ Bbase,
        float* __restrict__ C, __half* __restrict__ Ch,
        int K, int lda, int ldb, int ldc,
        int mode, const void* __restrict__ aux, int outKind,
        int grouped, size_t expStride)
{
    const int m0 = blockIdx.y * 128;
    const int n0 = blockIdx.x * 128;
    const __half* B = Bbase;
    if (grouped) {
        if (m0 >= g_seg[NEXPERT]) return;
        int e = 0;
        while (g_seg[e + 1] <= m0) e++;
        B += (size_t)e * expStride;
    }

    extern __shared__ __align__(16) char hsm[];
    const uint32_t sb = (uint32_t)__cvta_generic_to_shared(hsm);
    const uint32_t sbB = sb + NSTG * ASTG;

    const int tid = threadIdx.x;
    const int wid = tid >> 5, lane = tid & 31;
    const int wm = (wid >> 2) * 64;
    const int wn = (wid & 3) * 32;
    const int lr = lane >> 2, lc = lane & 3;      // epilogue coords
    const int q = lane >> 3, r8 = lane & 7;       // ldmatrix quadrant coords

    const uint32_t aoff = (uint32_t)((wm + ((q & 1) << 3) + r8) * ASTR + ((q >> 1) << 4));
    const uint32_t boff = (uint32_t)((((q & 1) << 3) + r8) * BSTR + ((wn + ((q >> 1) << 3)) << 1));

    float acc[4][4][4];
    #pragma unroll
    for (int i = 0; i < 4; i++)
        #pragma unroll
        for (int j = 0; j < 4; j++)
            #pragma unroll
            for (int v = 0; v < 4; v++) acc[i][j][v] = 0.f;

    const int nIter = K / TK;

    auto issue = [&](int st, int k0) {
        #pragma unroll
        for (int w = 0; w < 4; w++) {       // A: 128 rows x 8 chunks
            const int id = tid + w * 256;
            const int row = id >> 3, ch = id & 7;
            cp16(sb + st * ASTG + row * ASTR + ch * 16,
                 A + (size_t)(m0 + row) * lda + k0 + ch * 8);
        }
        #pragma unroll
        for (int w = 0; w < 4; w++) {       // B: 64 k-rows x 16 chunks
            const int id = tid + w * 256;
            const int kr = id >> 4, ch = id & 15;
            cp16(sbB + st * BSTG + kr * BSTR + ch * 16,
                 B + (size_t)(k0 + kr) * ldb + n0 + ch * 8);
        }
        asm volatile("cp.async.commit_group;" ::: "memory");
    };

    issue(0, 0);
    if (nIter > 1) issue(1, TK);

    for (int it = 0; it < nIter; it++) {
        if (it + 2 < nIter) issue((it + 2) % NSTG, (it + 2) * TK);
        if (it + 3 <= nIter) {
            asm volatile("cp.async.wait_group 2;" ::: "memory");
        } else if (it + 2 <= nIter) {
            asm volatile("cp.async.wait_group 1;" ::: "memory");
        } else {
            asm volatile("cp.async.wait_group 0;" ::: "memory");
        }
        __syncthreads();

        const int st = it % NSTG;
        const uint32_t aBase = sb + st * ASTG + aoff;
        const uint32_t bBase = sbB + st * BSTG + boff;
        #pragma unroll
        for (int ks = 0; ks < 4; ks++) {
            unsigned a[4][4], bt[2][4];
            #pragma unroll
            for (int mt = 0; mt < 4; mt++)
                ldsm_x4(a[mt], aBase + mt * (16 * ASTR) + ks * 32);
            #pragma unroll
            for (int g = 0; g < 2; g++)
                ldsm_x4t(bt[g], bBase + ks * (16 * BSTR) + g * 32);
            #pragma unroll
            for (int mt = 0; mt < 4; mt++)
                #pragma unroll
                for (int nt = 0; nt < 4; nt++)
                    mma_f16(acc[mt][nt], a[mt], &bt[nt >> 1][(nt & 1) * 2]);
        }
        __syncthreads();
    }

    // epilogue
    const float* aux32 = (const float*)aux;
    const __half* aux16 = (const __half*)aux;
    #pragma unroll
    for (int mt = 0; mt < 4; mt++) {
        #pragma unroll
        for (int nt = 0; nt < 4; nt++) {
            const int row = m0 + wm + mt * 16 + lr;
            const int col = n0 + wn + nt * 8 + lc * 2;
            float2 v0 = make_float2(acc[mt][nt][0], acc[mt][nt][1]);   // row
            float2 v1 = make_float2(acc[mt][nt][2], acc[mt][nt][3]);   // row+8
            if (mode == 1) {
                const float2 r0 = *reinterpret_cast<const float2*>(aux32 + (size_t)row * ldc + col);
                const float2 r1 = *reinterpret_cast<const float2*>(aux32 + (size_t)(row + 8) * ldc + col);
                v0.x += r0.x; v0.y += r0.y;
                v1.x += r1.x; v1.y += r1.y;
            } else if (mode == 2) {
                const float b0 = aux32[col], b1 = aux32[col + 1];
                v0.x = softplusf(v0.x + b0); v0.y = softplusf(v0.y + b1);
                v1.x = softplusf(v1.x + b0); v1.y = softplusf(v1.y + b1);
            } else if (mode == 4) {
                const float2 g0 = __half22float2(
                    *reinterpret_cast<const __half2*>(aux16 + (size_t)row * ldc + col));
                const float2 g1 = __half22float2(
                    *reinterpret_cast<const __half2*>(aux16 + (size_t)(row + 8) * ldc + col));
                v0.x *= siluf(g0.x); v0.y *= siluf(g0.y);
                v1.x *= siluf(g1.x); v1.y *= siluf(g1.y);
            }
            if (outKind != 1) {
                *reinterpret_cast<float2*>(C + (size_t)row * ldc + col) = v0;
                *reinterpret_cast<float2*>(C + (size_t)(row + 8) * ldc + col) = v1;
            }
            if (outKind >= 1) {
                *reinterpret_cast<__half2*>(Ch + (size_t)row * ldc + col) =
                    __floats2half2_rn(v0.x, v0.y);
                *reinterpret_cast<__half2*>(Ch + (size_t)(row + 8) * ldc + col) =
                    __floats2half2_rn(v1.x, v1.y);
            }
        }
    }
}

// ---------------- causal depthwise conv + silu (fp16 in/out) ----------------
__global__ void __launch_bounds__(256) k_conv(const float* __restrict__ cw,
                                              const float* __restrict__ cb)
{
    const int idx = blockIdx.x * 256 + threadIdx.x;   // over TT*DINNER
    const int c = idx & (DINNER - 1);
    const int tg = idx >> 11;                          // token index
    const int l = tg & (LSEQ - 1);
    float acc = cb[c];
    #pragma unroll
    for (int k = 0; k < 4; k++) {
        const int dl = l - 3 + k;
        if (dl >= 0)
            acc += cw[c * 4 + k] *
                   __half2float(g_xzh[(size_t)(tg - 3 + k) * (2 * DINNER) + c]);
    }
    g_xich[(size_t)tg * DINNER + c] = __float2half(siluf(acc));
}

// ---------------- selective scan: 16 channels/block, 16 lanes/channel --------
__global__ void __launch_bounds__(256) k_scan(const float* __restrict__ A_log,
                                              const float* __restrict__ D_skip)
{
    const int b = blockIdx.x >> 7;               // batch
    const int cg = blockIdx.x & 127;             // channel group
    const int tid = threadIdx.x;
    const int c = cg * 16 + (tid >> 4);
    const int n = tid & 15;

    const float A = -__expf(A_log[c * DSTATE + n]);
    const float D = D_skip[c];
    float h = 0.f;

    const float*  dlt = g_delta + (size_t)b * LSEQ * DINNER + c;
    const __half* xin = g_xich  + (size_t)b * LSEQ * DINNER + c;
    const float*  dbc = g_dbc   + (size_t)b * LSEQ * LDDBC;
    const __half* zin = g_xzh   + (size_t)b * LSEQ * (2 * DINNER) + DINNER + c;
    __half* yout = g_y2h + (size_t)b * LSEQ * DINNER + c;

    for (int l = 0; l < LSEQ; l++) {
        const float d  = dlt[(size_t)l * DINNER];
        const float x  = __half2float(xin[(size_t)l * DINNER]);
        const float Bn = dbc[(size_t)l * LDDBC + DTRANK + n];
        const float Cn = dbc[(size_t)l * LDDBC + DTRANK + DSTATE + n];
        const float dA = __expf(d * A);
        h = dA * h + (d * x) * Bn;
        float v = h * Cn;
        v += __shfl_xor_sync(0xffffffff, v, 1);
        v += __shfl_xor_sync(0xffffffff, v, 2);
        v += __shfl_xor_sync(0xffffffff, v, 4);
        v += __shfl_xor_sync(0xffffffff, v, 8);
        if (n == 0) {
            const float z = __half2float(zin[(size_t)l * (2 * DINNER)]);
            yout[(size_t)l * DINNER] = __float2half((v + D * x) * siluf(z));
        }
    }
}

// ---------------- MoE bookkeeping ----------------
__global__ void k_zero8() { if (threadIdx.x < NEXPERT) g_cnt[threadIdx.x] = 0; }

__global__ void k_seg()
{
    int s = 0;
    g_seg[0] = 0;
    for (int e = 0; e < NEXPERT; e++) {
        g_cur[e] = s;
        s += ((g_cnt[e] + 127) / 128) * 128;
        g_seg[e + 1] = s;
    }
}

__global__ void __launch_bounds__(256) k_assign()
{
    const int idx = blockIdx.x * 256 + threadIdx.x;   // over TT*2
    const int e = g_sel[idx];
    const int r = atomicAdd(&g_cur[e], 1);
    g_tok[r] = idx >> 1;
    g_rowmap[idx] = r;
}

__global__ void __launch_bounds__(256) k_gather()
{
    const int row = blockIdx.x;
    if (row >= g_seg[NEXPERT]) return;
    int e = 0;
    while (g_seg[e + 1] <= row) e++;
    __half2* dst = reinterpret_cast<__half2*>(g_Xgh + (size_t)row * DMODEL);
    const int c = threadIdx.x * 4;
    if (row >= g_cur[e]) {   // padding row -> zero
        dst[threadIdx.x * 2]     = __floats2half2_rn(0.f, 0.f);
        dst[threadIdx.x * 2 + 1] = __floats2half2_rn(0.f, 0.f);
        return;
    }
    const float4 v = *reinterpret_cast<const float4*>(
        g_hn + (size_t)g_tok[row] * DMODEL + c);
    dst[threadIdx.x * 2]     = __floats2half2_rn(v.x, v.y);
    dst[threadIdx.x * 2 + 1] = __floats2half2_rn(v.z, v.w);
}

__global__ void __launch_bounds__(256) k_combine(float* __restrict__ out)
{
    const int t = blockIdx.x;
    const int r0 = g_rowmap[t * 2], r1 = g_rowmap[t * 2 + 1];
    const float w0 = g_wts[t * 2], w1 = g_wts[t * 2 + 1];
    const int c = threadIdx.x * 4;
    float4 a = *reinterpret_cast<const float4*>(g_h2 + (size_t)t * DMODEL + c);
    float4 y0 = *reinterpret_cast<const float4*>(g_Y + (size_t)r0 * DMODEL + c);
    float4 y1 = *reinterpret_cast<const float4*>(g_Y + (size_t)r1 * DMODEL + c);
    a.x += w0 * y0.x + w1 * y1.x;
    a.y += w0 * y0.y + w1 * y1.y;
    a.z += w0 * y0.z + w1 * y1.z;
    a.w += w0 * y0.w + w1 * y1.w;
    *reinterpret_cast<float4*>(out + (size_t)t * DMODEL + c) = a;
}

// ---------------- launch ----------------
extern "C" void kernel_launch(void* const* d_in, const int* in_sizes, int n_in,
                              void* d_out, int out_size)
{
    const float* x          = (const float*)d_in[0];
    const float* rms1_w     = (const float*)d_in[1];
    const float* rms2_w     = (const float*)d_in[2];
    const float* in_proj_w  = (const float*)d_in[3];
    const float* conv_w     = (const float*)d_in[4];
    const float* conv_b     = (const float*)d_in[5];
    const float* x_proj_w   = (const float*)d_in[6];
    const float* dt_proj_w  = (const float*)d_in[7];
    const float* dt_proj_b  = (const float*)d_in[8];
    const float* A_log      = (const float*)d_in[9];
    const float* D_skip     = (const float*)d_in[10];
    const float* out_proj_w = (const float*)d_in[11];
    const float* router_w   = (const float*)d_in[12];
    const float* Wg         = (const float*)d_in[13];
    const float* Wu         = (const float*)d_in[14];
    const float* Wd         = (const float*)d_in[15];
    float* out = (float*)d_out;

    cudaFuncSetAttribute(k_hgemm, cudaFuncAttributeMaxDynamicSharedMemorySize, H_SMEM);

    float *p_dbc, *p_delta, *p_h2, *p_hn, *p_Y;
    __half *p_h1h, *p_xzh, *p_xich, *p_dbch, *p_y2h, *p_Xgh, *p_Gh0, *p_Gh;
    __half *p_ipwh, *p_xpwh, *p_dtwh, *p_opwh, *p_Wgh, *p_Wuh, *p_Wdh;
    cudaGetSymbolAddress((void**)&p_dbc, g_dbc);
    cudaGetSymbolAddress((void**)&p_delta, g_delta);
    cudaGetSymbolAddress((void**)&p_h2, g_h2);
    cudaGetSymbolAddress((void**)&p_hn, g_hn);
    cudaGetSymbolAddress((void**)&p_Y, g_Y);
    cudaGetSymbolAddress((void**)&p_h1h, g_h1h);
    cudaGetSymbolAddress((void**)&p_xzh, g_xzh);
    cudaGetSymbolAddress((void**)&p_xich, g_xich);
    cudaGetSymbolAddress((void**)&p_dbch, g_dbch);
    cudaGetSymbolAddress((void**)&p_y2h, g_y2h);
    cudaGetSymbolAddress((void**)&p_Xgh, g_Xgh);
    cudaGetSymbolAddress((void**)&p_Gh0, g_Gh0);
    cudaGetSymbolAddress((void**)&p_Gh, g_Gh);
    cudaGetSymbolAddress((void**)&p_ipwh, g_ipwh);
    cudaGetSymbolAddress((void**)&p_xpwh, g_xpwh);
    cudaGetSymbolAddress((void**)&p_dtwh, g_dtwh);
    cudaGetSymbolAddress((void**)&p_opwh, g_opwh);
    cudaGetSymbolAddress((void**)&p_Wgh, g_Wgh);
    cudaGetSymbolAddress((void**)&p_Wuh, g_Wuh);
    cudaGetSymbolAddress((void**)&p_Wdh, g_Wdh);

    // ---- fork: MoE weight converts on a side stream (independent branch) ----
    cudaStream_t s2;
    cudaStreamCreateWithFlags(&s2, cudaStreamNonBlocking);
    cudaEvent_t evFork, evJoin;
    cudaEventCreateWithFlags(&evFork, cudaEventDisableTiming);
    cudaEventCreateWithFlags(&evJoin, cudaEventDisableTiming);
    cudaEventRecord(evFork, 0);
    cudaStreamWaitEvent(s2, evFork, 0);
    k_cvt<<<NEXPERT * 1024 * 4096 / 4096, 256, 0, s2>>>(Wg, p_Wgh, NEXPERT * 1024 * 4096 / 4);
    k_cvt<<<NEXPERT * 1024 * 4096 / 4096, 256, 0, s2>>>(Wu, p_Wuh, NEXPERT * 1024 * 4096 / 4);
    k_cvt<<<NEXPERT * 4096 * 1024 / 4096, 256, 0, s2>>>(Wd, p_Wdh, NEXPERT * 4096 * 1024 / 4);
    cudaEventRecord(evJoin, s2);

    // ---- main chain (default stream) ----
    // small weight converts + rmsnorm
    k_cvt<<<1024 * 4096 / 4096, 256>>>(in_proj_w, p_ipwh, 1024 * 4096 / 4);
    k_cvtpad<<<DINNER * LDDBC / 256, 256>>>(x_proj_w, p_xpwh);
    k_cvt<<<64 * 2048 / 4096, 256>>>(dt_proj_w, p_dtwh, 64 * 2048 / 4);
    k_cvt<<<2048 * 1024 / 4096, 256>>>(out_proj_w, p_opwh, 2048 * 1024 / 4);
    k_rmsnorm<<<TT, 256>>>(x, rms1_w, nullptr, p_h1h);
    // in_proj: [TT,1024]@[1024,4096] -> fp16 xz
    k_hgemm<<<dim3(32, 32), 256, H_SMEM>>>(
        p_h1h, p_ipwh, nullptr, p_xzh, DMODEL, DMODEL, 2 * DINNER, 2 * DINNER,
        0, nullptr, 1, 0, 0);
    // depthwise conv + silu (fp16)
    k_conv<<<TT * DINNER / 256, 256>>>(conv_w, conv_b);
    // x_proj: [TT,2048] @ [2048,128] -> fp32 dbc + fp16 dbch
    k_hgemm<<<dim3(1, 32), 256, H_SMEM>>>(
        p_xich, p_xpwh, p_dbc, p_dbch, DINNER, DINNER, LDDBC, LDDBC,
        0, nullptr, 2, 0, 0);
    // dt_proj + softplus: [TT,64] @ [64,2048] -> fp32 delta
    k_hgemm<<<dim3(16, 32), 256, H_SMEM>>>(
        p_dbch, p_dtwh, p_delta, nullptr, DTRANK, LDDBC, DINNER, DINNER,
        2, dt_proj_b, 0, 0, 0);
    // selective scan + gating -> fp16 y2h
    k_scan<<<NBATCH * (DINNER / 16), 256>>>(A_log, D_skip);
    // out_proj + residual: [TT,2048] @ [2048,1024] + x -> fp32 h2
    k_hgemm<<<dim3(8, 32), 256, H_SMEM>>>(
        p_y2h, p_opwh, p_h2, nullptr, DINNER, DINNER, DMODEL, DMODEL,
        1, x, 0, 0, 0);
    // rmsnorm2 fused with router (needs g_cnt zeroed first)
    k_zero8<<<1, 32>>>();
    k_rms_router<<<TT, 256>>>(p_h2, rms2_w, p_hn, router_w);
    k_seg<<<1, 1>>>();
    k_assign<<<TT * 2 / 256, 256>>>();
    k_gather<<<MAXR, 256>>>();

    // ---- join: MoE weights must be converted before the grouped GEMMs ----
    cudaStreamWaitEvent(0, evJoin, 0);

    // MoE grouped GEMMs (gate fp16 end-to-end; GLU fused via mode 4)
    k_hgemm<<<dim3(FFND / 128, MAXR / 128), 256, H_SMEM>>>(
        p_Xgh, p_Wgh, nullptr, p_Gh0, DMODEL, DMODEL, FFND, FFND,
        0, nullptr, 1, 1, (size_t)DMODEL * FFND);
    k_hgemm<<<dim3(FFND / 128, MAXR / 128), 256, H_SMEM>>>(
        p_Xgh, p_Wuh, nullptr, p_Gh, DMODEL, DMODEL, FFND, FFND,
        4, p_Gh0, 1, 1, (size_t)DMODEL * FFND);
    k_hgemm<<<dim3(DMODEL / 128, MAXR / 128), 256, H_SMEM>>>(
        p_Gh, p_Wdh, p_Y, nullptr, FFND, FFND, DMODEL, DMODEL,
        0, nullptr, 0, 1, (size_t)FFND * DMODEL);
    // combine + residual -> out
    k_combine<<<TT, 256>>>(out);
}